// round 1
// baseline (speedup 1.0000x reference)
#include <cuda_runtime.h>
#include <cuda_bf16.h>
#include <cstdint>
#include <cstddef>

#define NN 4096
#define FF 128
#define GSPLIT 8

// ---------------- scratch (static device allocations; no cudaMalloc) ----------------
__device__ float g_XW[NN * FF];
__device__ float g_P2[NN * FF];
__device__ float g_srow[NN];
__device__ float g_scol[NN];
__device__ float g_ec1[NN];   // exp(0.01*s_col[j])
__device__ float g_ec2[NN];   // exp(s_col[j])
__device__ float g_keys[NN];  // sorted s_row
__device__ float g_er1s[NN];  // exp(0.01*sorted_s_row)
__device__ float g_er2s[NN];  // exp(sorted_s_row)
__device__ int   g_perm[NN];
__device__ int   g_mj[NN];
__device__ float g_att[(size_t)NN * NN];            // 67 MB
__device__ float g_part[(size_t)GSPLIT * NN * FF];  // split-K partials

// ---------------- K1: XW = X @ W  (16 rows per block) ----------------
__global__ __launch_bounds__(128) void k_xw(const float* __restrict__ X,
                                            const float* __restrict__ W) {
    __shared__ float xr[16][FF];
    int j = threadIdx.x;
    int i0 = blockIdx.x * 16;
#pragma unroll
    for (int r = 0; r < 16; r++) xr[r][j] = X[(size_t)(i0 + r) * FF + j];
    __syncthreads();
    float acc[16];
#pragma unroll
    for (int r = 0; r < 16; r++) acc[r] = 0.f;
    for (int k = 0; k < FF; k++) {
        float w = W[k * FF + j];
#pragma unroll
        for (int r = 0; r < 16; r++) acc[r] += xr[r][k] * w;
    }
#pragma unroll
    for (int r = 0; r < 16; r++) g_XW[(size_t)(i0 + r) * FF + j] = acc[r];
}

// ---------------- K2: s_row, s_col, exp factors ----------------
__global__ __launch_bounds__(128) void k_sums(const float* __restrict__ avec) {
    int i = blockIdx.x;
    int t = threadIdx.x;
    float xw = g_XW[(size_t)i * FF + t];
    float p_col = xw * avec[t];        // a[0, :F]   -> s_col
    float p_row = xw * avec[FF + t];   // a[0, F:]   -> s_row
#pragma unroll
    for (int off = 16; off; off >>= 1) {
        p_col += __shfl_down_sync(0xffffffffu, p_col, off);
        p_row += __shfl_down_sync(0xffffffffu, p_row, off);
    }
    __shared__ float sc4[4], sr4[4];
    if ((t & 31) == 0) { sc4[t >> 5] = p_col; sr4[t >> 5] = p_row; }
    __syncthreads();
    if (t == 0) {
        float scv = sc4[0] + sc4[1] + sc4[2] + sc4[3];
        float srv = sr4[0] + sr4[1] + sr4[2] + sr4[3];
        g_srow[i] = srv;
        g_scol[i] = scv;
        g_ec1[i] = expf(0.01f * scv);
        g_ec2[i] = expf(scv);
    }
}

// ---------------- K3: bitonic sort of s_row (single block) ----------------
__global__ __launch_bounds__(1024) void k_sort() {
    __shared__ float kk[NN];
    __shared__ int   id[NN];
    int tid = threadIdx.x;
    for (int r = tid; r < NN; r += 1024) { kk[r] = g_srow[r]; id[r] = r; }
    __syncthreads();
    for (int sz = 2; sz <= NN; sz <<= 1) {
        for (int st = sz >> 1; st > 0; st >>= 1) {
#pragma unroll
            for (int q = 0; q < 4; q++) {
                int i = tid + q * 1024;
                int j = i ^ st;
                if (j > i) {
                    bool up = ((i & sz) == 0);
                    float ki = kk[i], kj = kk[j];
                    bool swap = up ? (ki > kj) : (ki < kj);
                    if (swap) {
                        kk[i] = kj; kk[j] = ki;
                        int ti = id[i]; id[i] = id[j]; id[j] = ti;
                    }
                }
            }
            __syncthreads();
        }
    }
    for (int r = tid; r < NN; r += 1024) {
        float kv = kk[r];
        g_keys[r] = kv;
        g_perm[r] = id[r];
        g_er1s[r] = expf(0.01f * kv);
        g_er2s[r] = expf(kv);
    }
}

// ---------------- K4: m_j = #{k : s_row[k] < -s_col[j]} via binary search ----------------
__global__ void k_mj() {
    int j = blockIdx.x * blockDim.x + threadIdx.x;
    if (j < NN) {
        float t = -g_scol[j];
        int lo = 0, hi = NN;
        while (lo < hi) {
            int mid = (lo + hi) >> 1;
            if (g_keys[mid] < t) lo = mid + 1; else hi = mid;
        }
        g_mj[j] = lo;
    }
}

// ---------------- K5: per-row prefix-scan -> num -> att (one block per row i) ----------------
__global__ __launch_bounds__(1024) void k_scan(const float* __restrict__ A) {
    // smem union: phase1 sm[0..4095] = A row; phase2 sPb[0..4096], sPc[0..4096], warp sums
    __shared__ float sm[2 * (NN + 1) + 64];
    float* sPb = sm;
    float* sPc = sm + (NN + 1);
    float* wb  = sm + 2 * (NN + 1);
    float* wc  = wb + 32;

    int row = blockIdx.x;
    int tid = threadIdx.x;
    int lane = tid & 31;
    int wid = tid >> 5;

    const float* Arow = A + (size_t)row * NN;
    for (int r = tid; r < NN; r += 1024) sm[r] = Arow[r];
    __syncthreads();

    // gather in sorted order; compute b (0.01-branch) and c (full-branch) terms
    int base = tid * 4;
    float b[4], c[4];
#pragma unroll
    for (int q = 0; q < 4; q++) {
        int r = base + q;
        float av = sm[g_perm[r]];
        b[q] = av * g_er1s[r];
        c[q] = av * g_er2s[r];
    }
    float lb = b[0] + b[1] + b[2] + b[3];
    float lc = c[0] + c[1] + c[2] + c[3];

    // warp inclusive scan of thread sums
    float sb = lb, sc = lc;
#pragma unroll
    for (int off = 1; off < 32; off <<= 1) {
        float t1 = __shfl_up_sync(0xffffffffu, sb, off);
        float t2 = __shfl_up_sync(0xffffffffu, sc, off);
        if (lane >= off) { sb += t1; sc += t2; }
    }
    if (lane == 31) { wb[wid] = sb; wc[wid] = sc; }
    __syncthreads();  // all gathers done + warp sums written

    if (wid == 0) {
        float vb = wb[lane], vc = wc[lane];
#pragma unroll
        for (int off = 1; off < 32; off <<= 1) {
            float t1 = __shfl_up_sync(0xffffffffu, vb, off);
            float t2 = __shfl_up_sync(0xffffffffu, vc, off);
            if (lane >= off) { vb += t1; vc += t2; }
        }
        wb[lane] = vb; wc[lane] = vc;
    }
    __syncthreads();

    float offb = (wid ? wb[wid - 1] : 0.f) + (sb - lb);
    float offc = (wid ? wc[wid - 1] : 0.f) + (sc - lc);

    // write exclusive prefixes (overwrites the A-row region — safe after syncs)
    float rb = offb, rc = offc;
#pragma unroll
    for (int q = 0; q < 4; q++) {
        sPb[base + q] = rb; rb += b[q];
        sPc[base + q] = rc; rc += c[q];
    }
    if (tid == 1023) { sPb[NN] = rb; sPc[NN] = rc; }
    __syncthreads();

    float Ctot = sPc[NN];
    float srow_i = g_srow[row];
    size_t orow = (size_t)row * NN;
    for (int j = tid; j < NN; j += 1024) {
        int m = g_mj[j];
        float num = g_ec1[j] * sPb[m] + g_ec2[j] * (Ctot - sPc[m]);
        float t = srow_i + g_scol[j];
        float den = expf(t >= 0.f ? t : 0.01f * t);
        g_att[orow + j] = (num != 0.f) ? (den / num) : 0.f;
    }
}

// ---------------- K6: split-K SIMT fp32 GEMM  C_part[s] = Am[64 rows] @ B ----------------
// Am: [4096,4096], B: [4096,128]. grid (64, GSPLIT), 256 threads.
__global__ __launch_bounds__(256) void k_gemm(const float* __restrict__ Am,
                                              const float* __restrict__ B) {
    __shared__ float sA[16 * 68];   // [k][m], stride 68
    __shared__ float sB[16 * 128];  // [k][n]
    int tid = threadIdx.x;
    int m0 = blockIdx.x * 64;
    int s = blockIdx.y;
    int kbeg = s * (NN / GSPLIT);   // 512-wide K chunk
    int tx = tid & 31, ty = tid >> 5;

    int ar = tid >> 2;            // 0..63
    int ac4 = (tid & 3) * 4;      // 0,4,8,12
    int br = tid >> 5;            // 0..7
    int bc4 = (tid & 31) * 4;     // 0..124

    float acc[8][4];
#pragma unroll
    for (int r = 0; r < 8; r++)
#pragma unroll
        for (int cidx = 0; cidx < 4; cidx++) acc[r][cidx] = 0.f;

    for (int kk = kbeg; kk < kbeg + NN / GSPLIT; kk += 16) {
        float4 av = *(const float4*)(Am + (size_t)(m0 + ar) * NN + kk + ac4);
        float4 bv0 = *(const float4*)(B + (size_t)(kk + br) * FF + bc4);
        float4 bv1 = *(const float4*)(B + (size_t)(kk + br + 8) * FF + bc4);
        __syncthreads();
        sA[(ac4 + 0) * 68 + ar] = av.x;
        sA[(ac4 + 1) * 68 + ar] = av.y;
        sA[(ac4 + 2) * 68 + ar] = av.z;
        sA[(ac4 + 3) * 68 + ar] = av.w;
        *(float4*)(sB + br * 128 + bc4) = bv0;
        *(float4*)(sB + (br + 8) * 128 + bc4) = bv1;
        __syncthreads();
#pragma unroll
        for (int k2 = 0; k2 < 16; k2++) {
            float4 bb = *(const float4*)(sB + k2 * 128 + tx * 4);
            float4 a0 = *(const float4*)(sA + k2 * 68 + ty * 8);
            float4 a1 = *(const float4*)(sA + k2 * 68 + ty * 8 + 4);
            float a[8] = {a0.x, a0.y, a0.z, a0.w, a1.x, a1.y, a1.z, a1.w};
            float bv[4] = {bb.x, bb.y, bb.z, bb.w};
#pragma unroll
            for (int r = 0; r < 8; r++)
#pragma unroll
                for (int cidx = 0; cidx < 4; cidx++) acc[r][cidx] += a[r] * bv[cidx];
        }
    }
    float* Cp = g_part + (size_t)s * (NN * FF);
#pragma unroll
    for (int r = 0; r < 8; r++) {
        int rowi = m0 + ty * 8 + r;
        *(float4*)(Cp + (size_t)rowi * FF + tx * 4) =
            make_float4(acc[r][0], acc[r][1], acc[r][2], acc[r][3]);
    }
}

// ---------------- K7: reduce split-K partials ----------------
__global__ void k_reduce(float* __restrict__ out) {
    int i = blockIdx.x * blockDim.x + threadIdx.x;
    if (i < NN * FF) {
        float s = 0.f;
#pragma unroll
        for (int p = 0; p < GSPLIT; p++) s += g_part[(size_t)p * (NN * FF) + i];
        out[i] = s;
    }
}

// ---------------- launcher ----------------
extern "C" void kernel_launch(void* const* d_in, const int* in_sizes, int n_in,
                              void* d_out, int out_size) {
    const float *X = nullptr, *A = nullptr, *W = nullptr, *av = nullptr;
    for (int i = 0; i < n_in; i++) {
        switch (in_sizes[i]) {
            case NN * FF:      X = (const float*)d_in[i]; break;
            case NN * NN:      A = (const float*)d_in[i]; break;  // 16777216
            case FF * FF:      W = (const float*)d_in[i]; break;
            case 2 * FF:       av = (const float*)d_in[i]; break;
            default: break;
        }
    }
    float* H = (float*)d_out;

    float* dP2 = nullptr;
    cudaGetSymbolAddress((void**)&dP2, g_P2);

    // 1. XW = X @ W
    k_xw<<<NN / 16, 128>>>(X, W);
    // 2. s_row/s_col + exp factors
    k_sums<<<NN, 128>>>(av);
    // 3. sort s_row
    k_sort<<<1, 1024>>>();
    // 4. thresholds
    k_mj<<<16, 256>>>();
    // 5. att via prefix-scan trick (replaces the 137-GFLOP GEMM)
    k_scan<<<NN, 1024>>>(A);
    // 6. P2 = att @ XW
    {
        float* dAtt = nullptr;
        cudaGetSymbolAddress((void**)&dAtt, g_att);
        float* dXW = nullptr;
        cudaGetSymbolAddress((void**)&dXW, g_XW);
        dim3 grid(NN / 64, GSPLIT);
        k_gemm<<<grid, 256>>>(dAtt, dXW);
        k_reduce<<<(NN * FF + 255) / 256, 256>>>(dP2);
        // 7. H = A @ P2
        k_gemm<<<grid, 256>>>(A, dP2);
        k_reduce<<<(NN * FF + 255) / 256, 256>>>(H);
    }
}

// round 3
// speedup vs baseline: 1.5144x; 1.5144x over previous
#include <cuda_runtime.h>
#include <cuda_bf16.h>
#include <cstdint>
#include <cstddef>

#define NN 4096
#define FF 128
#define SPLITK 4
#define BK 32
#define KTILES ((NN / SPLITK) / BK)   // 32 k-tiles per CTA

// ---------------- scratch ----------------
__device__ float g_XW[NN * FF];
__device__ float g_srow[NN];
__device__ float g_scol[NN];
__device__ float g_ec1[NN];
__device__ float g_ec2[NN];
__device__ float g_keys[NN];
__device__ float g_er1s[NN];
__device__ float g_er2s[NN];
__device__ int   g_perm[NN];
__device__ int   g_mj[NN];
__device__ float g_att[(size_t)NN * NN];
__device__ float g_part[(size_t)SPLITK * NN * FF];
__device__ __nv_bfloat16 g_Bh[NN * FF];   // B operand hi, [k=4096][n=128]
__device__ __nv_bfloat16 g_Bl[NN * FF];   // B operand lo

// ---------------- mma/ldmatrix helpers ----------------
__device__ __forceinline__ uint32_t smem_u32(const void* p) {
    uint32_t a;
    asm("{ .reg .u64 t; cvta.to.shared.u64 t, %1; cvt.u32.u64 %0, t; }" : "=r"(a) : "l"(p));
    return a;
}
__device__ __forceinline__ void ldsm4(uint32_t* r, uint32_t a) {
    asm volatile("ldmatrix.sync.aligned.m8n8.x4.shared.b16 {%0,%1,%2,%3}, [%4];"
        : "=r"(r[0]), "=r"(r[1]), "=r"(r[2]), "=r"(r[3]) : "r"(a));
}
__device__ __forceinline__ void ldsm4t(uint32_t* r, uint32_t a) {
    asm volatile("ldmatrix.sync.aligned.m8n8.x4.trans.shared.b16 {%0,%1,%2,%3}, [%4];"
        : "=r"(r[0]), "=r"(r[1]), "=r"(r[2]), "=r"(r[3]) : "r"(a));
}
__device__ __forceinline__ void mma16816(float* d, const uint32_t* a, const uint32_t* b) {
    asm volatile(
        "mma.sync.aligned.m16n8k16.row.col.f32.bf16.bf16.f32 "
        "{%0,%1,%2,%3}, {%4,%5,%6,%7}, {%8,%9}, {%0,%1,%2,%3};"
        : "+f"(d[0]), "+f"(d[1]), "+f"(d[2]), "+f"(d[3])
        : "r"(a[0]), "r"(a[1]), "r"(a[2]), "r"(a[3]), "r"(b[0]), "r"(b[1]));
}
__device__ __forceinline__ void split_bf16(float f, uint16_t& h, uint16_t& l) {
    __nv_bfloat16 hb = __float2bfloat16_rn(f);
    float r = f - __bfloat162float(hb);
    __nv_bfloat16 lb = __float2bfloat16_rn(r);
    h = *(uint16_t*)&hb;
    l = *(uint16_t*)&lb;
}

// ---------------- K1: XW = X @ W (+ bf16 hi/lo of XW as B operand) ----------------
__global__ __launch_bounds__(128) void k_xw(const float* __restrict__ X,
                                            const float* __restrict__ W) {
    __shared__ float xr[16][FF];
    int j = threadIdx.x;
    int i0 = blockIdx.x * 16;
#pragma unroll
    for (int r = 0; r < 16; r++) xr[r][j] = X[(size_t)(i0 + r) * FF + j];
    __syncthreads();
    float acc[16];
#pragma unroll
    for (int r = 0; r < 16; r++) acc[r] = 0.f;
    for (int k = 0; k < FF; k++) {
        float w = W[k * FF + j];
#pragma unroll
        for (int r = 0; r < 16; r++) acc[r] += xr[r][k] * w;
    }
#pragma unroll
    for (int r = 0; r < 16; r++) {
        size_t idx = (size_t)(i0 + r) * FF + j;
        g_XW[idx] = acc[r];
        uint16_t h, l;
        split_bf16(acc[r], h, l);
        g_Bh[idx] = *(__nv_bfloat16*)&h;
        g_Bl[idx] = *(__nv_bfloat16*)&l;
    }
}

// ---------------- K2: s_row, s_col + exp factors ----------------
__global__ __launch_bounds__(128) void k_sums(const float* __restrict__ avec) {
    int i = blockIdx.x;
    int t = threadIdx.x;
    float xw = g_XW[(size_t)i * FF + t];
    float p_col = xw * avec[t];
    float p_row = xw * avec[FF + t];
#pragma unroll
    for (int off = 16; off; off >>= 1) {
        p_col += __shfl_down_sync(0xffffffffu, p_col, off);
        p_row += __shfl_down_sync(0xffffffffu, p_row, off);
    }
    __shared__ float sc4[4], sr4[4];
    if ((t & 31) == 0) { sc4[t >> 5] = p_col; sr4[t >> 5] = p_row; }
    __syncthreads();
    if (t == 0) {
        float scv = sc4[0] + sc4[1] + sc4[2] + sc4[3];
        float srv = sr4[0] + sr4[1] + sr4[2] + sr4[3];
        g_srow[i] = srv;
        g_scol[i] = scv;
        g_ec1[i] = expf(0.01f * scv);
        g_ec2[i] = expf(scv);
    }
}

// ---------------- K3: bitonic sort of s_row ----------------
__global__ __launch_bounds__(1024) void k_sort() {
    __shared__ float kk[NN];
    __shared__ int   id[NN];
    int tid = threadIdx.x;
    for (int r = tid; r < NN; r += 1024) { kk[r] = g_srow[r]; id[r] = r; }
    __syncthreads();
    for (int sz = 2; sz <= NN; sz <<= 1) {
        for (int st = sz >> 1; st > 0; st >>= 1) {
#pragma unroll
            for (int q = 0; q < 4; q++) {
                int i = tid + q * 1024;
                int j = i ^ st;
                if (j > i) {
                    bool up = ((i & sz) == 0);
                    float ki = kk[i], kj = kk[j];
                    bool swap = up ? (ki > kj) : (ki < kj);
                    if (swap) {
                        kk[i] = kj; kk[j] = ki;
                        int ti = id[i]; id[i] = id[j]; id[j] = ti;
                    }
                }
            }
            __syncthreads();
        }
    }
    for (int r = tid; r < NN; r += 1024) {
        float kv = kk[r];
        g_keys[r] = kv;
        g_perm[r] = id[r];
        g_er1s[r] = expf(0.01f * kv);
        g_er2s[r] = expf(kv);
    }
}

// ---------------- K4: thresholds ----------------
__global__ void k_mj() {
    int j = blockIdx.x * blockDim.x + threadIdx.x;
    if (j < NN) {
        float t = -g_scol[j];
        int lo = 0, hi = NN;
        while (lo < hi) {
            int mid = (lo + hi) >> 1;
            if (g_keys[mid] < t) lo = mid + 1; else hi = mid;
        }
        g_mj[j] = lo;
    }
}

// ---------------- K5: per-row prefix-scan -> att ----------------
__global__ __launch_bounds__(1024) void k_scan(const float* __restrict__ A) {
    __shared__ float sm[2 * (NN + 1) + 64];
    float* sPb = sm;
    float* sPc = sm + (NN + 1);
    float* wb  = sm + 2 * (NN + 1);
    float* wc  = wb + 32;

    int row = blockIdx.x;
    int tid = threadIdx.x;
    int lane = tid & 31;
    int wid = tid >> 5;

    const float* Arow = A + (size_t)row * NN;
    for (int r = tid; r < NN; r += 1024) sm[r] = Arow[r];
    __syncthreads();

    int base = tid * 4;
    float b[4], c[4];
#pragma unroll
    for (int q = 0; q < 4; q++) {
        int r = base + q;
        float av = sm[g_perm[r]];
        b[q] = av * g_er1s[r];
        c[q] = av * g_er2s[r];
    }
    float lb = b[0] + b[1] + b[2] + b[3];
    float lc = c[0] + c[1] + c[2] + c[3];

    float sb = lb, sc = lc;
#pragma unroll
    for (int off = 1; off < 32; off <<= 1) {
        float t1 = __shfl_up_sync(0xffffffffu, sb, off);
        float t2 = __shfl_up_sync(0xffffffffu, sc, off);
        if (lane >= off) { sb += t1; sc += t2; }
    }
    if (lane == 31) { wb[wid] = sb; wc[wid] = sc; }
    __syncthreads();

    if (wid == 0) {
        float vb = wb[lane], vc = wc[lane];
#pragma unroll
        for (int off = 1; off < 32; off <<= 1) {
            float t1 = __shfl_up_sync(0xffffffffu, vb, off);
            float t2 = __shfl_up_sync(0xffffffffu, vc, off);
            if (lane >= off) { vb += t1; vc += t2; }
        }
        wb[lane] = vb; wc[lane] = vc;
    }
    __syncthreads();

    float offb = (wid ? wb[wid - 1] : 0.f) + (sb - lb);
    float offc = (wid ? wc[wid - 1] : 0.f) + (sc - lc);

    float rb = offb, rc = offc;
#pragma unroll
    for (int q = 0; q < 4; q++) {
        sPb[base + q] = rb; rb += b[q];
        sPc[base + q] = rc; rc += c[q];
    }
    if (tid == 1023) { sPb[NN] = rb; sPc[NN] = rc; }
    __syncthreads();

    float Ctot = sPc[NN];
    float srow_i = g_srow[row];
    size_t orow = (size_t)row * NN;
    for (int j = tid; j < NN; j += 1024) {
        int m = g_mj[j];
        float num = g_ec1[j] * sPb[m] + g_ec2[j] * (Ctot - sPc[m]);
        float t = srow_i + g_scol[j];
        float den = expf(t >= 0.f ? t : 0.01f * t);
        g_att[orow + j] = (num != 0.f) ? (den / num) : 0.f;
    }
}

// ---------------- K6: HMMA split-bf16 GEMM ----------------
// Cpart[s][m][n] = sum_{k in split s} Ag[m][k] * B[k][n]
// Ag fp32 [4096][4096]; B = g_Bh/g_Bl bf16 [4096][128].
// CTA tile 128x128, BK=32, 256 threads (8 warps = 2x4), double-buffered smem.
// smem per stage: Ah 8KB | Al 8KB | Bh 8KB | Bl 8KB = 32KB; x2 stages = 64KB.
#define STAGE_BYTES 32768
#define AH_OFF 0
#define AL_OFF 8192
#define BH_OFF 16384
#define BL_OFF 24576

__global__ __launch_bounds__(256) void mm_gemm(const float* __restrict__ Ag,
                                               float* __restrict__ Cpart) {
    extern __shared__ char smem[];
    uint32_t sb = smem_u32(smem);
    int tid = threadIdx.x;
    int lane = tid & 31;
    int wid = tid >> 5;
    int wm = wid >> 2;        // 0..1  (m warp)
    int wn = wid & 3;         // 0..3  (n warp)
    int m0 = blockIdx.x * 128;
    int s = blockIdx.y;
    int kbeg = s * (NN / SPLITK);

    // per-thread load coords
    // A: chunk = tid + q*256 (q=0,1); row=chunk>>2 (0..127), c=chunk&3 (8-float chunk)
    int a_row0 = tid >> 2, a_c = tid & 3;
    // B: chunk = tid + q*256; k=chunk>>4 (0..31), c=chunk&15 (8-bf16 chunk)
    int b_k0 = tid >> 4, b_c = tid & 15;

    float4 pa[4];      // A prefetch: 2 chunks x 2 float4
    uint4 pbh[2], pbl[2];

    const __nv_bfloat16* Bh = g_Bh;
    const __nv_bfloat16* Bl = g_Bl;

    // ---- load tile 0 into regs ----
    {
        int kt = kbeg;
#pragma unroll
        for (int q = 0; q < 2; q++) {
            int row = a_row0 + q * 64;
            const float* p = Ag + (size_t)(m0 + row) * NN + kt + a_c * 8;
            pa[q * 2 + 0] = *(const float4*)p;
            pa[q * 2 + 1] = *(const float4*)(p + 4);
        }
#pragma unroll
        for (int q = 0; q < 2; q++) {
            int k = b_k0 + q * 16;
            pbh[q] = *(const uint4*)(Bh + (size_t)(kt + k) * FF + b_c * 8);
            pbl[q] = *(const uint4*)(Bl + (size_t)(kt + k) * FF + b_c * 8);
        }
    }

    float acc[4][4][4];
#pragma unroll
    for (int i = 0; i < 4; i++)
#pragma unroll
        for (int j = 0; j < 4; j++)
#pragma unroll
            for (int r = 0; r < 4; r++) acc[i][j][r] = 0.f;

    // store prefetched tile into a smem stage
    auto store_stage = [&](int stg) {
        uint32_t base = sb + stg * STAGE_BYTES;
#pragma unroll
        for (int q = 0; q < 2; q++) {
            int row = a_row0 + q * 64;
            int sw = (row >> 1) & 3;
            uint32_t off = base + row * 64 + ((a_c ^ sw) << 4);
            float f[8] = {pa[q*2].x, pa[q*2].y, pa[q*2].z, pa[q*2].w,
                          pa[q*2+1].x, pa[q*2+1].y, pa[q*2+1].z, pa[q*2+1].w};
            uint16_t h[8], l[8];
#pragma unroll
            for (int e = 0; e < 8; e++) split_bf16(f[e], h[e], l[e]);
            uint4 hv, lv;
            hv.x = h[0] | (h[1] << 16); hv.y = h[2] | (h[3] << 16);
            hv.z = h[4] | (h[5] << 16); hv.w = h[6] | (h[7] << 16);
            lv.x = l[0] | (l[1] << 16); lv.y = l[2] | (l[3] << 16);
            lv.z = l[4] | (l[5] << 16); lv.w = l[6] | (l[7] << 16);
            *(uint4*)(smem + (off - sb) + AH_OFF) = hv;
            *(uint4*)(smem + (off - sb) + AL_OFF) = lv;
        }
#pragma unroll
        for (int q = 0; q < 2; q++) {
            int k = b_k0 + q * 16;
            int sc = b_c ^ (k & 7);
            uint32_t off = (uint32_t)(stg * STAGE_BYTES) + k * 256 + (sc << 4);
            *(uint4*)(smem + off + BH_OFF) = pbh[q];
            *(uint4*)(smem + off + BL_OFF) = pbl[q];
        }
    };

    store_stage(0);
    __syncthreads();

    for (int t = 0; t < KTILES; t++) {
        int stg = t & 1;
        // prefetch next tile
        if (t + 1 < KTILES) {
            int kt = kbeg + (t + 1) * BK;
#pragma unroll
            for (int q = 0; q < 2; q++) {
                int row = a_row0 + q * 64;
                const float* p = Ag + (size_t)(m0 + row) * NN + kt + a_c * 8;
                pa[q * 2 + 0] = *(const float4*)p;
                pa[q * 2 + 1] = *(const float4*)(p + 4);
            }
#pragma unroll
            for (int q = 0; q < 2; q++) {
                int k = b_k0 + q * 16;
                pbh[q] = *(const uint4*)(Bh + (size_t)(kt + k) * FF + b_c * 8);
                pbl[q] = *(const uint4*)(Bl + (size_t)(kt + k) * FF + b_c * 8);
            }
        }
        // compute on stage stg
        uint32_t abase = sb + stg * STAGE_BYTES;
#pragma unroll
        for (int ks = 0; ks < 2; ks++) {
            uint32_t ah[4][4], al[4][4], bhf[2][4], blf[2][4];
#pragma unroll
            for (int mt = 0; mt < 4; mt++) {
                int row = wm * 64 + mt * 16 + (lane & 7) + ((lane >> 3) & 1) * 8;
                int c = 2 * ks + (lane >> 4);
                uint32_t addr = abase + row * 64 + (((c ^ ((row >> 1) & 3))) << 4);
                ldsm4(ah[mt], addr + AH_OFF);
                ldsm4(al[mt], addr + AL_OFF);
            }
#pragma unroll
            for (int nh = 0; nh < 2; nh++) {
                int k = ks * 16 + (lane & 7) + ((lane >> 3) & 1) * 8;
                int c = ((wn * 32 + nh * 16) >> 3) + (lane >> 4);
                uint32_t addr = abase + k * 256 + (((c ^ (k & 7))) << 4);
                ldsm4t(bhf[nh], addr + BH_OFF);
                ldsm4t(blf[nh], addr + BL_OFF);
            }
#pragma unroll
            for (int mt = 0; mt < 4; mt++)
#pragma unroll
                for (int nt = 0; nt < 4; nt++) {
                    int nh = nt >> 1;
                    const uint32_t* bh2 = &bhf[nh][(nt & 1) * 2];
                    const uint32_t* bl2 = &blf[nh][(nt & 1) * 2];
                    mma16816(acc[mt][nt], ah[mt], bh2);
                    mma16816(acc[mt][nt], ah[mt], bl2);
                    mma16816(acc[mt][nt], al[mt], bh2);
                }
        }
        // store prefetched into other stage
        if (t + 1 < KTILES) store_stage((t + 1) & 1);
        __syncthreads();
    }

    // epilogue
    float* C = Cpart + (size_t)s * (NN * FF);
#pragma unroll
    for (int mt = 0; mt < 4; mt++) {
#pragma unroll
        for (int nt = 0; nt < 4; nt++) {
            int row = m0 + wm * 64 + mt * 16 + (lane >> 2);
            int col = wn * 32 + nt * 8 + (lane & 3) * 2;
            *(float2*)(C + (size_t)row * FF + col) =
                make_float2(acc[mt][nt][0], acc[mt][nt][1]);
            *(float2*)(C + (size_t)(row + 8) * FF + col) =
                make_float2(acc[mt][nt][2], acc[mt][nt][3]);
        }
    }
}

// ---------------- K7a: reduce partials -> fp32 out ----------------
__global__ void k_reduce(float* __restrict__ out) {
    int i = blockIdx.x * blockDim.x + threadIdx.x;
    if (i < NN * FF) {
        float s = 0.f;
#pragma unroll
        for (int p = 0; p < SPLITK; p++) s += g_part[(size_t)p * (NN * FF) + i];
        out[i] = s;
    }
}

// ---------------- K7b: reduce partials -> bf16 hi/lo B operand ----------------
__global__ void k_reduce_conv() {
    int i = blockIdx.x * blockDim.x + threadIdx.x;
    if (i < NN * FF) {
        float s = 0.f;
#pragma unroll
        for (int p = 0; p < SPLITK; p++) s += g_part[(size_t)p * (NN * FF) + i];
        uint16_t h, l;
        split_bf16(s, h, l);
        g_Bh[i] = *(__nv_bfloat16*)&h;
        g_Bl[i] = *(__nv_bfloat16*)&l;
    }
}

// ---------------- launcher ----------------
extern "C" void kernel_launch(void* const* d_in, const int* in_sizes, int n_in,
                              void* d_out, int out_size) {
    const float *X = nullptr, *A = nullptr, *W = nullptr, *av = nullptr;
    for (int i = 0; i < n_in; i++) {
        switch (in_sizes[i]) {
            case NN * FF: X = (const float*)d_in[i]; break;
            case NN * NN: A = (const float*)d_in[i]; break;
            case FF * FF: W = (const float*)d_in[i]; break;
            case 2 * FF:  av = (const float*)d_in[i]; break;
            default: break;
        }
    }
    float* H = (float*)d_out;

    float *dAtt = nullptr, *dPart = nullptr;
    cudaGetSymbolAddress((void**)&dAtt, g_att);
    cudaGetSymbolAddress((void**)&dPart, g_part);

    cudaFuncSetAttribute(mm_gemm, cudaFuncAttributeMaxDynamicSharedMemorySize,
                         2 * STAGE_BYTES);

    k_xw<<<NN / 16, 128>>>(X, W);
    k_sums<<<NN, 128>>>(av);
    k_sort<<<1, 1024>>>();
    k_mj<<<16, 256>>>();
    k_scan<<<NN, 1024>>>(A);

    dim3 grid(NN / 128, SPLITK);
    // P2 = att @ XW  (B = bf16(XW) from k_xw)
    mm_gemm<<<grid, 256, 2 * STAGE_BYTES>>>(dAtt, dPart);
    k_reduce_conv<<<(NN * FF + 255) / 256, 256>>>();  // partials -> bf16 P2 (B operand)
    // H = A @ P2
    mm_gemm<<<grid, 256, 2 * STAGE_BYTES>>>(A, dPart);
    k_reduce<<<(NN * FF + 255) / 256, 256>>>(H);
}

// round 4
// speedup vs baseline: 1.6097x; 1.0629x over previous
#include <cuda_runtime.h>
#include <cuda_bf16.h>
#include <cstdint>
#include <cstddef>

#define NN 4096
#define FF 128
#define SPLITK 4
#define BK 32
#define KTILES ((NN / SPLITK) / BK)   // 32
#define STAGES 4
#define STAGE_BYTES 32768
#define AH_OFF 0
#define AL_OFF 8192
#define BH_OFF 16384
#define BL_OFF 24576

// ---------------- scratch ----------------
__device__ float g_srow[NN];
__device__ float g_scol[NN];
__device__ float g_ec1[NN];    // exp(0.01*scol)
__device__ float g_ec2[NN];    // exp(scol)
__device__ float g_er1u[NN];   // exp(0.01*srow) (unsorted)
__device__ float g_er2u[NN];   // exp(srow)
__device__ float g_er1s[NN];   // sorted-order exp factors
__device__ float g_er2s[NN];
__device__ int   g_perm[NN];
__device__ int   g_mj[NN];
__device__ float g_part[(size_t)SPLITK * NN * FF];
__device__ __nv_bfloat16 g_Bh[NN * FF];          // B operand hi [k][n]
__device__ __nv_bfloat16 g_Bl[NN * FF];
__device__ __nv_bfloat16 g_AttH[(size_t)NN * NN]; // att hi (GEMM1 A)
__device__ __nv_bfloat16 g_AttL[(size_t)NN * NN];
__device__ __nv_bfloat16 g_AH[(size_t)NN * NN];   // input A hi (GEMM2 A)
__device__ __nv_bfloat16 g_AL[(size_t)NN * NN];

// ---------------- helpers ----------------
__device__ __forceinline__ uint32_t smem_u32(const void* p) {
    uint32_t a;
    asm("{ .reg .u64 t; cvta.to.shared.u64 t, %1; cvt.u32.u64 %0, t; }" : "=r"(a) : "l"(p));
    return a;
}
__device__ __forceinline__ void ldsm4(uint32_t* r, uint32_t a) {
    asm volatile("ldmatrix.sync.aligned.m8n8.x4.shared.b16 {%0,%1,%2,%3}, [%4];"
        : "=r"(r[0]), "=r"(r[1]), "=r"(r[2]), "=r"(r[3]) : "r"(a));
}
__device__ __forceinline__ void ldsm4t(uint32_t* r, uint32_t a) {
    asm volatile("ldmatrix.sync.aligned.m8n8.x4.trans.shared.b16 {%0,%1,%2,%3}, [%4];"
        : "=r"(r[0]), "=r"(r[1]), "=r"(r[2]), "=r"(r[3]) : "r"(a));
}
__device__ __forceinline__ void mma16816(float* d, const uint32_t* a, const uint32_t* b) {
    asm volatile(
        "mma.sync.aligned.m16n8k16.row.col.f32.bf16.bf16.f32 "
        "{%0,%1,%2,%3}, {%4,%5,%6,%7}, {%8,%9}, {%0,%1,%2,%3};"
        : "+f"(d[0]), "+f"(d[1]), "+f"(d[2]), "+f"(d[3])
        : "r"(a[0]), "r"(a[1]), "r"(a[2]), "r"(a[3]), "r"(b[0]), "r"(b[1]));
}
__device__ __forceinline__ void split_bf16(float f, uint16_t& h, uint16_t& l) {
    __nv_bfloat16 hb = __float2bfloat16_rn(f);
    float r = f - __bfloat162float(hb);
    __nv_bfloat16 lb = __float2bfloat16_rn(r);
    h = *(uint16_t*)&hb;
    l = *(uint16_t*)&lb;
}
#define CP16(dst, src) \
    asm volatile("cp.async.cg.shared.global [%0], [%1], 16;" :: "r"(dst), "l"(src))
#define CP_COMMIT() asm volatile("cp.async.commit_group;" ::: "memory")
#define CP_WAIT2() asm volatile("cp.async.wait_group 2;" ::: "memory")

// ---------------- K1: XW = X @ W, emit bf16(XW) + s_row/s_col + exp factors ----------------
__global__ __launch_bounds__(128) void k_xw(const float* __restrict__ X,
                                            const float* __restrict__ W,
                                            const float* __restrict__ av) {
    __shared__ float xr[16][FF];
    int j = threadIdx.x;
    int i0 = blockIdx.x * 16;
#pragma unroll
    for (int r = 0; r < 16; r++) xr[r][j] = X[(size_t)(i0 + r) * FF + j];
    __syncthreads();
    float acc[16];
#pragma unroll
    for (int r = 0; r < 16; r++) acc[r] = 0.f;
    for (int k = 0; k < FF; k++) {
        float w = W[k * FF + j];
#pragma unroll
        for (int r = 0; r < 16; r++) acc[r] += xr[r][k] * w;
    }
#pragma unroll
    for (int r = 0; r < 16; r++) {
        size_t idx = (size_t)(i0 + r) * FF + j;
        uint16_t h, l;
        split_bf16(acc[r], h, l);
        g_Bh[idx] = *(__nv_bfloat16*)&h;
        g_Bl[idx] = *(__nv_bfloat16*)&l;
    }
    float ac = av[j], ar = av[FF + j];
    int lane = j & 31, w4 = j >> 5;
    // s_col
    __syncthreads();
#pragma unroll
    for (int r = 0; r < 16; r++) xr[r][j] = acc[r] * ac;
    __syncthreads();
#pragma unroll
    for (int rr = 0; rr < 4; rr++) {
        int r = w4 * 4 + rr;
        float v = xr[r][lane] + xr[r][lane + 32] + xr[r][lane + 64] + xr[r][lane + 96];
#pragma unroll
        for (int off = 16; off; off >>= 1) v += __shfl_down_sync(0xffffffffu, v, off);
        if (lane == 0) {
            g_scol[i0 + r] = v;
            g_ec1[i0 + r] = expf(0.01f * v);
            g_ec2[i0 + r] = expf(v);
        }
    }
    // s_row
    __syncthreads();
#pragma unroll
    for (int r = 0; r < 16; r++) xr[r][j] = acc[r] * ar;
    __syncthreads();
#pragma unroll
    for (int rr = 0; rr < 4; rr++) {
        int r = w4 * 4 + rr;
        float v = xr[r][lane] + xr[r][lane + 32] + xr[r][lane + 64] + xr[r][lane + 96];
#pragma unroll
        for (int off = 16; off; off >>= 1) v += __shfl_down_sync(0xffffffffu, v, off);
        if (lane == 0) {
            g_srow[i0 + r] = v;
            g_er1u[i0 + r] = expf(0.01f * v);
            g_er2u[i0 + r] = expf(v);
        }
    }
}

// ---------------- K2: bitonic sort of s_row + sorted exp factors + m_j ----------------
__global__ __launch_bounds__(1024) void k_sort() {
    __shared__ float kk[NN];
    __shared__ int   id[NN];
    int tid = threadIdx.x;
    for (int r = tid; r < NN; r += 1024) { kk[r] = g_srow[r]; id[r] = r; }
    __syncthreads();
    for (int sz = 2; sz <= NN; sz <<= 1) {
        for (int st = sz >> 1; st > 0; st >>= 1) {
#pragma unroll
            for (int q = 0; q < 4; q++) {
                int i = tid + q * 1024;
                int j = i ^ st;
                if (j > i) {
                    bool up = ((i & sz) == 0);
                    float ki = kk[i], kj = kk[j];
                    bool swap = up ? (ki > kj) : (ki < kj);
                    if (swap) {
                        kk[i] = kj; kk[j] = ki;
                        int ti = id[i]; id[i] = id[j]; id[j] = ti;
                    }
                }
            }
            __syncthreads();
        }
    }
    for (int r = tid; r < NN; r += 1024) {
        float kv = kk[r];
        g_perm[r] = id[r];
        g_er1s[r] = expf(0.01f * kv);
        g_er2s[r] = expf(kv);
    }
    // m_j = #{k : sorted_srow[k] < -s_col[j]} (binary search in smem)
    for (int j = tid; j < NN; j += 1024) {
        float t = -g_scol[j];
        int lo = 0, hi = NN;
        while (lo < hi) {
            int mid = (lo + hi) >> 1;
            if (kk[mid] < t) lo = mid + 1; else hi = mid;
        }
        g_mj[j] = lo;
    }
}

// ---------------- K3: per-row scan -> att (bf16 hi/lo) + A bf16 hi/lo ----------------
__global__ __launch_bounds__(1024) void k_scan(const float* __restrict__ A) {
    __shared__ float sm[2 * (NN + 1) + 64];
    float* sPb = sm;
    float* sPc = sm + (NN + 1);
    float* wb  = sm + 2 * (NN + 1);
    float* wc  = wb + 32;

    int row = blockIdx.x;
    int tid = threadIdx.x;
    int lane = tid & 31;
    int wid = tid >> 5;
    int base = tid * 4;
    size_t orow = (size_t)row * NN;

    // load A row (vectorized), stash in smem, emit bf16 hi/lo planes of A
    {
        float4 va = *(const float4*)(A + orow + base);
        sm[base + 0] = va.x; sm[base + 1] = va.y;
        sm[base + 2] = va.z; sm[base + 3] = va.w;
        uint16_t h[4], l[4];
        split_bf16(va.x, h[0], l[0]); split_bf16(va.y, h[1], l[1]);
        split_bf16(va.z, h[2], l[2]); split_bf16(va.w, h[3], l[3]);
        uint2 hv, lv;
        hv.x = h[0] | (h[1] << 16); hv.y = h[2] | (h[3] << 16);
        lv.x = l[0] | (l[1] << 16); lv.y = l[2] | (l[3] << 16);
        *(uint2*)((uint16_t*)g_AH + orow + base) = hv;
        *(uint2*)((uint16_t*)g_AL + orow + base) = lv;
    }
    __syncthreads();

    float b[4], c[4];
#pragma unroll
    for (int q = 0; q < 4; q++) {
        int r = base + q;
        float avv = sm[g_perm[r]];
        b[q] = avv * g_er1s[r];
        c[q] = avv * g_er2s[r];
    }
    float lb = b[0] + b[1] + b[2] + b[3];
    float lc = c[0] + c[1] + c[2] + c[3];

    float sb = lb, sc = lc;
#pragma unroll
    for (int off = 1; off < 32; off <<= 1) {
        float t1 = __shfl_up_sync(0xffffffffu, sb, off);
        float t2 = __shfl_up_sync(0xffffffffu, sc, off);
        if (lane >= off) { sb += t1; sc += t2; }
    }
    if (lane == 31) { wb[wid] = sb; wc[wid] = sc; }
    __syncthreads();
    if (wid == 0) {
        float vb = wb[lane], vc = wc[lane];
#pragma unroll
        for (int off = 1; off < 32; off <<= 1) {
            float t1 = __shfl_up_sync(0xffffffffu, vb, off);
            float t2 = __shfl_up_sync(0xffffffffu, vc, off);
            if (lane >= off) { vb += t1; vc += t2; }
        }
        wb[lane] = vb; wc[lane] = vc;
    }
    __syncthreads();

    float offb = (wid ? wb[wid - 1] : 0.f) + (sb - lb);
    float offc = (wid ? wc[wid - 1] : 0.f) + (sc - lc);
    float rb = offb, rc = offc;
#pragma unroll
    for (int q = 0; q < 4; q++) {
        sPb[base + q] = rb; rb += b[q];
        sPc[base + q] = rc; rc += c[q];
    }
    if (tid == 1023) { sPb[NN] = rb; sPc[NN] = rc; }
    __syncthreads();

    float Ctot = sPc[NN];
    float srow_i = g_srow[row];
    float er1u = g_er1u[row], er2u = g_er2u[row];
    {
        int4 mv = *(const int4*)(g_mj + base);
        float4 e1 = *(const float4*)(g_ec1 + base);
        float4 e2 = *(const float4*)(g_ec2 + base);
        float4 scv = *(const float4*)(g_scol + base);
        int   ms[4] = {mv.x, mv.y, mv.z, mv.w};
        float e1s[4] = {e1.x, e1.y, e1.z, e1.w};
        float e2s[4] = {e2.x, e2.y, e2.z, e2.w};
        float sc4[4] = {scv.x, scv.y, scv.z, scv.w};
        uint16_t h[4], l[4];
#pragma unroll
        for (int q = 0; q < 4; q++) {
            int m = ms[q];
            float num = e1s[q] * sPb[m] + e2s[q] * (Ctot - sPc[m]);
            float t = srow_i + sc4[q];
            float den = (t >= 0.f) ? er2u * e2s[q] : er1u * e1s[q];
            float att = (num != 0.f) ? __fdividef(den, num) : 0.f;
            split_bf16(att, h[q], l[q]);
        }
        uint2 hv, lv;
        hv.x = h[0] | (h[1] << 16); hv.y = h[2] | (h[3] << 16);
        lv.x = l[0] | (l[1] << 16); lv.y = l[2] | (l[3] << 16);
        *(uint2*)((uint16_t*)g_AttH + orow + base) = hv;
        *(uint2*)((uint16_t*)g_AttL + orow + base) = lv;
    }
}

// ---------------- K4: HMMA GEMM, pre-split operands, cp.async 4-stage pipeline ----------------
// Cpart[s][m][n] = sum_{k in split s} (Ah+Al)[m][k] * (Bh+Bl)[k][n]  (3-term emulation)
__global__ __launch_bounds__(256) void mm_gemm(const __nv_bfloat16* __restrict__ Ah,
                                               const __nv_bfloat16* __restrict__ Al,
                                               const __nv_bfloat16* __restrict__ Bh,
                                               const __nv_bfloat16* __restrict__ Bl,
                                               float* __restrict__ Cpart) {
    extern __shared__ char smem[];
    uint32_t sb = smem_u32(smem);
    int tid = threadIdx.x;
    int lane = tid & 31;
    int wid = tid >> 5;
    int wm = wid >> 2;
    int wn = wid & 3;
    int m0 = blockIdx.x * 128;
    int s = blockIdx.y;
    int kbeg = s * (NN / SPLITK);

    auto issue = [&](int t) {
        int kt = kbeg + t * BK;
        uint32_t st = sb + (t & (STAGES - 1)) * STAGE_BYTES;
#pragma unroll
        for (int q = 0; q < 2; q++) {
            int lin = tid + q * 256;
            int row = lin >> 2, c = lin & 3;
            uint32_t dst = st + row * 64 + (((c ^ ((row >> 1) & 3))) << 4);
            const __nv_bfloat16* srcH = Ah + (size_t)(m0 + row) * NN + kt + c * 8;
            const __nv_bfloat16* srcL = Al + (size_t)(m0 + row) * NN + kt + c * 8;
            CP16(dst + AH_OFF, srcH);
            CP16(dst + AL_OFF, srcL);
        }
#pragma unroll
        for (int q = 0; q < 2; q++) {
            int lin = tid + q * 256;
            int k = lin >> 4, c = lin & 15;
            uint32_t dst = st + k * 256 + (((c ^ (k & 7))) << 4);
            CP16(dst + BH_OFF, Bh + (size_t)(kt + k) * FF + c * 8);
            CP16(dst + BL_OFF, Bl + (size_t)(kt + k) * FF + c * 8);
        }
        CP_COMMIT();
    };

    issue(0); issue(1); issue(2);

    float acc[4][4][4];
#pragma unroll
    for (int i = 0; i < 4; i++)
#pragma unroll
        for (int j = 0; j < 4; j++)
#pragma unroll
            for (int r = 0; r < 4; r++) acc[i][j][r] = 0.f;

    for (int t = 0; t < KTILES; t++) {
        CP_WAIT2();
        __syncthreads();
        if (t + 3 < KTILES) issue(t + 3); else CP_COMMIT();

        uint32_t abase = sb + (t & (STAGES - 1)) * STAGE_BYTES;
#pragma unroll
        for (int ks = 0; ks < 2; ks++) {
            uint32_t ah[4][4], al[4][4], bhf[2][4], blf[2][4];
#pragma unroll
            for (int mt = 0; mt < 4; mt++) {
                int row = wm * 64 + mt * 16 + (lane & 7) + ((lane >> 3) & 1) * 8;
                int c = 2 * ks + (lane >> 4);
                uint32_t addr = abase + row * 64 + (((c ^ ((row >> 1) & 3))) << 4);
                ldsm4(ah[mt], addr + AH_OFF);
                ldsm4(al[mt], addr + AL_OFF);
            }
#pragma unroll
            for (int nh = 0; nh < 2; nh++) {
                int k = ks * 16 + (lane & 7) + ((lane >> 3) & 1) * 8;
                int c = ((wn * 32 + nh * 16) >> 3) + (lane >> 4);
                uint32_t addr = abase + k * 256 + (((c ^ (k & 7))) << 4);
                ldsm4t(bhf[nh], addr + BH_OFF);
                ldsm4t(blf[nh], addr + BL_OFF);
            }
#pragma unroll
            for (int mt = 0; mt < 4; mt++)
#pragma unroll
                for (int nt = 0; nt < 4; nt++) {
                    int nh = nt >> 1;
                    const uint32_t* bh2 = &bhf[nh][(nt & 1) * 2];
                    const uint32_t* bl2 = &blf[nh][(nt & 1) * 2];
                    mma16816(acc[mt][nt], ah[mt], bh2);
                    mma16816(acc[mt][nt], ah[mt], bl2);
                    mma16816(acc[mt][nt], al[mt], bh2);
                }
        }
    }

    float* C = Cpart + (size_t)s * (NN * FF);
#pragma unroll
    for (int mt = 0; mt < 4; mt++) {
#pragma unroll
        for (int nt = 0; nt < 4; nt++) {
            int row = m0 + wm * 64 + mt * 16 + (lane >> 2);
            int col = wn * 32 + nt * 8 + (lane & 3) * 2;
            *(float2*)(C + (size_t)row * FF + col) =
                make_float2(acc[mt][nt][0], acc[mt][nt][1]);
            *(float2*)(C + (size_t)(row + 8) * FF + col) =
                make_float2(acc[mt][nt][2], acc[mt][nt][3]);
        }
    }
}

// ---------------- K5a: reduce partials -> fp32 out ----------------
__global__ void k_reduce(float* __restrict__ out) {
    int i = blockIdx.x * blockDim.x + threadIdx.x;
    if (i < NN * FF) {
        float s = 0.f;
#pragma unroll
        for (int p = 0; p < SPLITK; p++) s += g_part[(size_t)p * (NN * FF) + i];
        out[i] = s;
    }
}

// ---------------- K5b: reduce partials -> bf16 hi/lo B operand ----------------
__global__ void k_reduce_conv() {
    int i = blockIdx.x * blockDim.x + threadIdx.x;
    if (i < NN * FF) {
        float s = 0.f;
#pragma unroll
        for (int p = 0; p < SPLITK; p++) s += g_part[(size_t)p * (NN * FF) + i];
        uint16_t h, l;
        split_bf16(s, h, l);
        g_Bh[i] = *(__nv_bfloat16*)&h;
        g_Bl[i] = *(__nv_bfloat16*)&l;
    }
}

// ---------------- launcher ----------------
extern "C" void kernel_launch(void* const* d_in, const int* in_sizes, int n_in,
                              void* d_out, int out_size) {
    const float *X = nullptr, *A = nullptr, *W = nullptr, *av = nullptr;
    for (int i = 0; i < n_in; i++) {
        switch (in_sizes[i]) {
            case NN * FF: X = (const float*)d_in[i]; break;
            case NN * NN: A = (const float*)d_in[i]; break;
            case FF * FF: W = (const float*)d_in[i]; break;
            case 2 * FF:  av = (const float*)d_in[i]; break;
            default: break;
        }
    }
    float* H = (float*)d_out;

    __nv_bfloat16 *dAttH, *dAttL, *dAH, *dAL, *dBh, *dBl;
    float* dPart;
    cudaGetSymbolAddress((void**)&dAttH, g_AttH);
    cudaGetSymbolAddress((void**)&dAttL, g_AttL);
    cudaGetSymbolAddress((void**)&dAH, g_AH);
    cudaGetSymbolAddress((void**)&dAL, g_AL);
    cudaGetSymbolAddress((void**)&dBh, g_Bh);
    cudaGetSymbolAddress((void**)&dBl, g_Bl);
    cudaGetSymbolAddress((void**)&dPart, g_part);

    cudaFuncSetAttribute(mm_gemm, cudaFuncAttributeMaxDynamicSharedMemorySize,
                         STAGES * STAGE_BYTES);

    k_xw<<<NN / 16, 128>>>(X, W, av);
    k_sort<<<1, 1024>>>();
    k_scan<<<NN, 1024>>>(A);

    dim3 grid(NN / 128, SPLITK);
    // P2 = att @ XW
    mm_gemm<<<grid, 256, STAGES * STAGE_BYTES>>>(dAttH, dAttL, dBh, dBl, dPart);
    k_reduce_conv<<<(NN * FF + 255) / 256, 256>>>();
    // H = A @ P2
    mm_gemm<<<grid, 256, STAGES * STAGE_BYTES>>>(dAH, dAL, dBh, dBl, dPart);
    k_reduce<<<(NN * FF + 255) / 256, 256>>>(H);
}